// round 2
// baseline (speedup 1.0000x reference)
#include <cuda_runtime.h>

// Batched GEMM (NT): out[b,n,m] = sum_e A[b,n,e] * B[b,m,e]
// b=8, n=m=2048, e=1024, fp32.
// Round 0: register-blocked SIMT SGEMM baseline.
//   - 128x128 block tile, 256 threads, 8x8 per-thread micro-tile
//   - K-tile = 8, smem stored [k][mn] (transposed on load)
//   - register double-buffer of the next global tile across the barrier

#define BN 128
#define BM 128
#define BK 8
#define TN 8
#define TM 8

__global__ __launch_bounds__(256, 2)
void bgemm_nt_kernel(const float* __restrict__ A,
                     const float* __restrict__ B,
                     float* __restrict__ C) {
    const int Nn = 2048, Mm = 2048, E = 1024;

    __shared__ float As[BK][BN];
    __shared__ float Bs[BK][BM];

    const int batch = blockIdx.z;
    const float* Ab = A + (size_t)batch * Nn * E;
    const float* Bb = B + (size_t)batch * Mm * E;
    float*       Cb = C + (size_t)batch * Nn * Mm;

    const int n0 = blockIdx.y * BN;
    const int m0 = blockIdx.x * BM;

    const int t   = threadIdx.x;
    const int row = t >> 1;        // 0..127: which row of the 128-row tile this thread loads
    const int kh  = (t & 1) * 4;   // 0 or 4: which half of the K-tile (float4)

    const int tx = t & 15;         // 0..15 -> m direction
    const int ty = t >> 4;         // 0..15 -> n direction

    // Global load pointers (each thread loads one float4 of A and one of B per K-tile)
    const float* aptr = Ab + (size_t)(n0 + row) * E + kh;
    const float* bptr = Bb + (size_t)(m0 + row) * E + kh;

    float acc[TN][TM];
#pragma unroll
    for (int i = 0; i < TN; i++)
#pragma unroll
        for (int j = 0; j < TM; j++) acc[i][j] = 0.0f;

    // Prologue: prefetch K-tile 0 into registers
    float4 apre = *(const float4*)aptr;
    float4 bpre = *(const float4*)bptr;

    for (int kt = 0; kt < E; kt += BK) {
        // Commit prefetched tile to shared (transposed: [k][row])
        As[kh + 0][row] = apre.x;
        As[kh + 1][row] = apre.y;
        As[kh + 2][row] = apre.z;
        As[kh + 3][row] = apre.w;
        Bs[kh + 0][row] = bpre.x;
        Bs[kh + 1][row] = bpre.y;
        Bs[kh + 2][row] = bpre.z;
        Bs[kh + 3][row] = bpre.w;
        __syncthreads();

        // Prefetch next K-tile (overlaps with the FMA block below)
        if (kt + BK < E) {
            apre = *(const float4*)(aptr + kt + BK);
            bpre = *(const float4*)(bptr + kt + BK);
        }

#pragma unroll
        for (int kk = 0; kk < BK; kk++) {
            float4 a0 = *(const float4*)&As[kk][ty * TN];
            float4 a1 = *(const float4*)&As[kk][ty * TN + 4];
            float4 b0 = *(const float4*)&Bs[kk][tx * TM];
            float4 b1 = *(const float4*)&Bs[kk][tx * TM + 4];
            float av[8] = {a0.x, a0.y, a0.z, a0.w, a1.x, a1.y, a1.z, a1.w};
            float bv[8] = {b0.x, b0.y, b0.z, b0.w, b1.x, b1.y, b1.z, b1.w};
#pragma unroll
            for (int i = 0; i < TN; i++)
#pragma unroll
                for (int j = 0; j < TM; j++)
                    acc[i][j] = fmaf(av[i], bv[j], acc[i][j]);
        }
        __syncthreads();
    }

    // Epilogue: write 8x8 micro-tile as float4 pairs
#pragma unroll
    for (int i = 0; i < TN; i++) {
        float* crow = Cb + (size_t)(n0 + ty * TN + i) * Mm + m0 + tx * TM;
        *(float4*)(crow + 0) = make_float4(acc[i][0], acc[i][1], acc[i][2], acc[i][3]);
        *(float4*)(crow + 4) = make_float4(acc[i][4], acc[i][5], acc[i][6], acc[i][7]);
    }
}

extern "C" void kernel_launch(void* const* d_in, const int* in_sizes, int n_in,
                              void* d_out, int out_size) {
    const float* A = (const float*)d_in[0];  // mat_0: [8, 2048, 1024]
    const float* B = (const float*)d_in[1];  // mat_1: [8, 2048, 1024]
    float* C = (float*)d_out;                // out:   [8, 2048, 2048]

    dim3 grid(2048 / BM, 2048 / BN, 8);
    bgemm_nt_kernel<<<grid, 256>>>(A, B, C);
}

// round 4
// speedup vs baseline: 1.3226x; 1.3226x over previous
#include <cuda_runtime.h>
#include <cuda_bf16.h>
#include <cstdint>

// out[b,n,m] = sum_e A[b,n,e]*B[b,m,e];  b=8, n=m=2048, e=1024, fp32.
// R3: mma.sync (sm_80-class HMMA, valid on plain sm_103 target) bf16-split-3x.
//   Pass 1: convert A,B fp32 -> (hi,lo) bf16 scratch.
//   Pass 2: 128x128 CTA tile, 8 warps x (64x32), K-chunk 32, 4-stage cp.async,
//           D += Ahi*Bhi + Ahi*Blo + Alo*Bhi  (fp32 accumulators in registers).

#define NB 8
#define NN 2048
#define MM 2048
#define EE 1024

#define TILE 128
#define KC 32              // bf16 k per chunk
#define NCHUNKS (EE / KC)  // 32
#define NSTAGE 4

// smem: per stage 4 tiles (Ahi,Alo,Bhi,Blo), each 128 rows x 40 bf16 (80B stride)
#define ROWSTRIDE 80       // bytes per smem row (40 bf16; conflict-free ldmatrix)
#define TILE_BYTES (128 * ROWSTRIDE)         // 10240
#define OFF_AHI 0
#define OFF_ALO (1 * TILE_BYTES)
#define OFF_BHI (2 * TILE_BYTES)
#define OFF_BLO (3 * TILE_BYTES)
#define STAGE_BYTES (4 * TILE_BYTES)         // 40960
#define SMEM_TOTAL (NSTAGE * STAGE_BYTES)    // 163840

#define ELEMS (NB * NN * EE)
__device__ __nv_bfloat16 g_Ahi[ELEMS];
__device__ __nv_bfloat16 g_Alo[ELEMS];
__device__ __nv_bfloat16 g_Bhi[ELEMS];
__device__ __nv_bfloat16 g_Blo[ELEMS];

__device__ __forceinline__ uint32_t smem_u32(const void* p) {
    uint32_t a;
    asm("{ .reg .u64 t; cvta.to.shared.u64 t, %1; cvt.u32.u64 %0, t; }" : "=r"(a) : "l"(p));
    return a;
}
__device__ __forceinline__ void cp16(uint32_t dst, const void* src) {
    asm volatile("cp.async.cg.shared.global [%0], [%1], 16;" :: "r"(dst), "l"(src));
}
__device__ __forceinline__ void ldm_x4(uint32_t* d, uint32_t addr) {
    asm volatile("ldmatrix.sync.aligned.m8n8.x4.shared.b16 {%0,%1,%2,%3}, [%4];"
                 : "=r"(d[0]), "=r"(d[1]), "=r"(d[2]), "=r"(d[3]) : "r"(addr));
}
__device__ __forceinline__ void mma16816(float* d, const uint32_t* a, uint32_t b0, uint32_t b1) {
    asm volatile(
        "mma.sync.aligned.m16n8k16.row.col.f32.bf16.bf16.f32 "
        "{%0,%1,%2,%3}, {%4,%5,%6,%7}, {%8,%9}, {%0,%1,%2,%3};"
        : "+f"(d[0]), "+f"(d[1]), "+f"(d[2]), "+f"(d[3])
        : "r"(a[0]), "r"(a[1]), "r"(a[2]), "r"(a[3]), "r"(b0), "r"(b1));
}

// ---- convert: fp32 -> bf16 hi + bf16 lo ----
__global__ __launch_bounds__(256)
void convert_kernel(const float* __restrict__ src,
                    __nv_bfloat16* __restrict__ hi,
                    __nv_bfloat16* __restrict__ lo) {
    size_t i = (size_t)blockIdx.x * blockDim.x + threadIdx.x;
    if (i >= ELEMS / 4) return;
    float4 v = ((const float4*)src)[i];
    __nv_bfloat16 h0 = __float2bfloat16_rn(v.x);
    __nv_bfloat16 h1 = __float2bfloat16_rn(v.y);
    __nv_bfloat16 h2 = __float2bfloat16_rn(v.z);
    __nv_bfloat16 h3 = __float2bfloat16_rn(v.w);
    __nv_bfloat16 l0 = __float2bfloat16_rn(v.x - __bfloat162float(h0));
    __nv_bfloat16 l1 = __float2bfloat16_rn(v.y - __bfloat162float(h1));
    __nv_bfloat16 l2 = __float2bfloat16_rn(v.z - __bfloat162float(h2));
    __nv_bfloat16 l3 = __float2bfloat16_rn(v.w - __bfloat162float(h3));
    ((__nv_bfloat162*)hi)[2 * i]     = __nv_bfloat162{h0, h1};
    ((__nv_bfloat162*)hi)[2 * i + 1] = __nv_bfloat162{h2, h3};
    ((__nv_bfloat162*)lo)[2 * i]     = __nv_bfloat162{l0, l1};
    ((__nv_bfloat162*)lo)[2 * i + 1] = __nv_bfloat162{l2, l3};
}

__global__ __launch_bounds__(256, 1)
void bgemm_mma_kernel(float* __restrict__ C) {
    extern __shared__ char smem[];
    const uint32_t sb = smem_u32(smem);
    const int tid = threadIdx.x;
    const int lane = tid & 31;
    const int wid = tid >> 5;
    const int wm = wid >> 2;   // 0..1  -> 64-row slab (n)
    const int wn = wid & 3;    // 0..3  -> 32-col slab (m)

    const int bz = blockIdx.z;
    const int n0 = blockIdx.y * TILE;
    const int m0 = blockIdx.x * TILE;

    const __nv_bfloat16* gAhi = g_Ahi + ((size_t)bz * NN + n0) * EE;
    const __nv_bfloat16* gAlo = g_Alo + ((size_t)bz * NN + n0) * EE;
    const __nv_bfloat16* gBhi = g_Bhi + ((size_t)bz * MM + m0) * EE;
    const __nv_bfloat16* gBlo = g_Blo + ((size_t)bz * MM + m0) * EE;

    auto load_stage = [&](int kc, int st) {
        const uint32_t base = sb + st * STAGE_BYTES;
        const int e0 = kc * KC;
#pragma unroll
        for (int j = 0; j < 2; j++) {
            int c = tid + 256 * j;        // 0..511
            int row = c >> 2, q = c & 3;  // q: which 16B of the 64B row
            uint32_t off = (uint32_t)(row * ROWSTRIDE + q * 16);
            size_t gs = (size_t)row * EE + e0 + q * 8;
            cp16(base + OFF_AHI + off, gAhi + gs);
            cp16(base + OFF_ALO + off, gAlo + gs);
            cp16(base + OFF_BHI + off, gBhi + gs);
            cp16(base + OFF_BLO + off, gBlo + gs);
        }
    };

    float acc[4][4][4];
#pragma unroll
    for (int mi = 0; mi < 4; mi++)
#pragma unroll
        for (int ni = 0; ni < 4; ni++)
#pragma unroll
            for (int q = 0; q < 4; q++) acc[mi][ni][q] = 0.0f;

    // prologue: 3 stages in flight
    load_stage(0, 0); asm volatile("cp.async.commit_group;" ::: "memory");
    load_stage(1, 1); asm volatile("cp.async.commit_group;" ::: "memory");
    load_stage(2, 2); asm volatile("cp.async.commit_group;" ::: "memory");

    // ldmatrix lane addressing
    const int xrow = (lane & 7) + ((lane >> 3) & 1) * 8;  // 0..15
    const uint32_t kb = ((lane >> 4) & 1) * 16;

    for (int i = 0; i < NCHUNKS; i++) {
        asm volatile("cp.async.wait_group 2;" ::: "memory");
        __syncthreads();
        if (i + 3 < NCHUNKS) load_stage(i + 3, (i + 3) & 3);
        asm volatile("cp.async.commit_group;" ::: "memory");

        const uint32_t stb = sb + (i & 3) * STAGE_BYTES;
        const uint32_t aRow = (uint32_t)((wm * 64 + xrow) * ROWSTRIDE) + kb;
        const uint32_t bRow = (uint32_t)((wn * 32 + xrow) * ROWSTRIDE) + kb;

#pragma unroll
        for (int kk = 0; kk < 2; kk++) {
            const uint32_t ko = kk * 32;  // 16 bf16 = 32B per k16 step
            uint32_t Ah[4][4], Al[4][4], Bh[2][4], Bl[2][4];
#pragma unroll
            for (int mi = 0; mi < 4; mi++)
                ldm_x4(Ah[mi], stb + OFF_AHI + aRow + (uint32_t)(mi * 16 * ROWSTRIDE) + ko);
#pragma unroll
            for (int nj = 0; nj < 2; nj++)
                ldm_x4(Bh[nj], stb + OFF_BHI + bRow + (uint32_t)(nj * 16 * ROWSTRIDE) + ko);
#pragma unroll
            for (int nj = 0; nj < 2; nj++)
                ldm_x4(Bl[nj], stb + OFF_BLO + bRow + (uint32_t)(nj * 16 * ROWSTRIDE) + ko);
#pragma unroll
            for (int mi = 0; mi < 4; mi++)
                ldm_x4(Al[mi], stb + OFF_ALO + aRow + (uint32_t)(mi * 16 * ROWSTRIDE) + ko);

#pragma unroll
            for (int mi = 0; mi < 4; mi++)
#pragma unroll
                for (int ni = 0; ni < 4; ni++) {
                    int nj = ni >> 1, w = ni & 1;
                    mma16816(acc[mi][ni], Ah[mi], Bh[nj][w], Bh[nj][w + 2]);
                }
#pragma unroll
            for (int mi = 0; mi < 4; mi++)
#pragma unroll
                for (int ni = 0; ni < 4; ni++) {
                    int nj = ni >> 1, w = ni & 1;
                    mma16816(acc[mi][ni], Ah[mi], Bl[nj][w], Bl[nj][w + 2]);
                }
#pragma unroll
            for (int mi = 0; mi < 4; mi++)
#pragma unroll
                for (int ni = 0; ni < 4; ni++) {
                    int nj = ni >> 1, w = ni & 1;
                    mma16816(acc[mi][ni], Al[mi], Bh[nj][w], Bh[nj][w + 2]);
                }
        }
        __syncthreads();
    }

    // epilogue: direct stores
    float* Cb = C + ((size_t)bz * NN + n0 + wm * 64) * MM + m0 + wn * 32;
    const int r = lane >> 2, cc = (lane & 3) * 2;
#pragma unroll
    for (int mi = 0; mi < 4; mi++)
#pragma unroll
        for (int ni = 0; ni < 4; ni++) {
            float* p0 = Cb + (size_t)(mi * 16 + r) * MM + ni * 8 + cc;
            float* p1 = p0 + 8 * MM;
            *(float2*)p0 = make_float2(acc[mi][ni][0], acc[mi][ni][1]);
            *(float2*)p1 = make_float2(acc[mi][ni][2], acc[mi][ni][3]);
        }
}

extern "C" void kernel_launch(void* const* d_in, const int* in_sizes, int n_in,
                              void* d_out, int out_size) {
    const float* A = (const float*)d_in[0];
    const float* B = (const float*)d_in[1];
    float* C = (float*)d_out;

    __nv_bfloat16 *ahi, *alo, *bhi, *blo;
    cudaGetSymbolAddress((void**)&ahi, g_Ahi);
    cudaGetSymbolAddress((void**)&alo, g_Alo);
    cudaGetSymbolAddress((void**)&bhi, g_Bhi);
    cudaGetSymbolAddress((void**)&blo, g_Blo);

    const int cvt_blocks = (ELEMS / 4 + 255) / 256;
    convert_kernel<<<cvt_blocks, 256>>>(A, ahi, alo);
    convert_kernel<<<cvt_blocks, 256>>>(B, bhi, blo);

    cudaFuncSetAttribute(bgemm_mma_kernel, cudaFuncAttributeMaxDynamicSharedMemorySize, SMEM_TOTAL);
    dim3 grid(MM / TILE, NN / TILE, NB);
    bgemm_mma_kernel<<<grid, 256, SMEM_TOTAL>>>(C);
}

// round 5
// speedup vs baseline: 2.1095x; 1.5949x over previous
#include <cuda_runtime.h>
#include <cuda_bf16.h>
#include <cstdint>

// out[b,n,m] = sum_e A[b,n,e]*B[b,m,e];  b=8, n=m=2048, e=1024, fp32.
// R4: mma.sync bf16-split-3x; KC=16, 4 stages, 2 CTAs/SM (16 warps/SM),
//     fused convert (2 launches total so ncu -s 5 lands on the GEMM).

#define NB 8
#define NN 2048
#define MM 2048
#define EE 1024

#define TILE 128
#define KC 16              // bf16 k per chunk
#define NCHUNKS (EE / KC)  // 64
#define NSTAGE 4

#define ROWSTRIDE 48       // 32B data + 16B pad; conflict-free ldmatrix
#define TILE_BYTES (128 * ROWSTRIDE)         // 6144
#define OFF_AHI 0
#define OFF_ALO (1 * TILE_BYTES)
#define OFF_BHI (2 * TILE_BYTES)
#define OFF_BLO (3 * TILE_BYTES)
#define STAGE_BYTES (4 * TILE_BYTES)         // 24576
#define SMEM_TOTAL (NSTAGE * STAGE_BYTES)    // 98304

#define ELEMS (NB * NN * EE)
__device__ __nv_bfloat16 g_Ahi[ELEMS];
__device__ __nv_bfloat16 g_Alo[ELEMS];
__device__ __nv_bfloat16 g_Bhi[ELEMS];
__device__ __nv_bfloat16 g_Blo[ELEMS];

__device__ __forceinline__ uint32_t smem_u32(const void* p) {
    uint32_t a;
    asm("{ .reg .u64 t; cvta.to.shared.u64 t, %1; cvt.u32.u64 %0, t; }" : "=r"(a) : "l"(p));
    return a;
}
__device__ __forceinline__ void cp16cg(uint32_t dst, const void* src) {
    asm volatile("cp.async.cg.shared.global [%0], [%1], 16;" :: "r"(dst), "l"(src));
}
__device__ __forceinline__ void cp16ca(uint32_t dst, const void* src) {
    asm volatile("cp.async.ca.shared.global [%0], [%1], 16;" :: "r"(dst), "l"(src));
}
__device__ __forceinline__ void ldm_x4(uint32_t* d, uint32_t addr) {
    asm volatile("ldmatrix.sync.aligned.m8n8.x4.shared.b16 {%0,%1,%2,%3}, [%4];"
                 : "=r"(d[0]), "=r"(d[1]), "=r"(d[2]), "=r"(d[3]) : "r"(addr));
}
__device__ __forceinline__ void mma16816(float* d, const uint32_t* a, uint32_t b0, uint32_t b1) {
    asm volatile(
        "mma.sync.aligned.m16n8k16.row.col.f32.bf16.bf16.f32 "
        "{%0,%1,%2,%3}, {%4,%5,%6,%7}, {%8,%9}, {%0,%1,%2,%3};"
        : "+f"(d[0]), "+f"(d[1]), "+f"(d[2]), "+f"(d[3])
        : "r"(a[0]), "r"(a[1]), "r"(a[2]), "r"(a[3]), "r"(b0), "r"(b1));
}

// ---- fused convert: both matrices in one launch ----
__global__ __launch_bounds__(256)
void convert_fused_kernel(const float* __restrict__ A, const float* __restrict__ B,
                          __nv_bfloat16* __restrict__ ahi, __nv_bfloat16* __restrict__ alo,
                          __nv_bfloat16* __restrict__ bhi, __nv_bfloat16* __restrict__ blo) {
    size_t i = (size_t)blockIdx.x * blockDim.x + threadIdx.x;
    const size_t quads = ELEMS / 4;
    if (i >= 2 * quads) return;
    const float* src;
    __nv_bfloat16 *hi, *lo;
    size_t j;
    if (i < quads) { src = A; hi = g_Ahi; lo = g_Alo; j = i; }
    else           { src = B; hi = g_Bhi; lo = g_Blo; j = i - quads; }
    (void)ahi; (void)alo; (void)bhi; (void)blo;
    float4 v = ((const float4*)src)[j];
    __nv_bfloat16 h0 = __float2bfloat16_rn(v.x);
    __nv_bfloat16 h1 = __float2bfloat16_rn(v.y);
    __nv_bfloat16 h2 = __float2bfloat16_rn(v.z);
    __nv_bfloat16 h3 = __float2bfloat16_rn(v.w);
    __nv_bfloat16 l0 = __float2bfloat16_rn(v.x - __bfloat162float(h0));
    __nv_bfloat16 l1 = __float2bfloat16_rn(v.y - __bfloat162float(h1));
    __nv_bfloat16 l2 = __float2bfloat16_rn(v.z - __bfloat162float(h2));
    __nv_bfloat16 l3 = __float2bfloat16_rn(v.w - __bfloat162float(h3));
    ((__nv_bfloat162*)hi)[2 * j]     = __nv_bfloat162{h0, h1};
    ((__nv_bfloat162*)hi)[2 * j + 1] = __nv_bfloat162{h2, h3};
    ((__nv_bfloat162*)lo)[2 * j]     = __nv_bfloat162{l0, l1};
    ((__nv_bfloat162*)lo)[2 * j + 1] = __nv_bfloat162{l2, l3};
}

__global__ __launch_bounds__(256, 2)
void bgemm_mma_kernel(float* __restrict__ C) {
    extern __shared__ char smem[];
    const uint32_t sb = smem_u32(smem);
    const int tid = threadIdx.x;
    const int lane = tid & 31;
    const int wid = tid >> 5;
    const int wm = wid >> 2;   // 0..1  -> 64-row slab (n)
    const int wn = wid & 3;    // 0..3  -> 32-col slab (m)

    const int bz = blockIdx.z;
    const int n0 = blockIdx.y * TILE;
    const int m0 = blockIdx.x * TILE;

    const __nv_bfloat16* gAhi = g_Ahi + ((size_t)bz * NN + n0) * EE;
    const __nv_bfloat16* gAlo = g_Alo + ((size_t)bz * NN + n0) * EE;
    const __nv_bfloat16* gBhi = g_Bhi + ((size_t)bz * MM + m0) * EE;
    const __nv_bfloat16* gBlo = g_Blo + ((size_t)bz * MM + m0) * EE;

    // each thread: 1 row-half per tile (128 rows x 2 halves = 256 = blockDim)
    auto load_stage = [&](int kc, int st) {
        const uint32_t base = sb + st * STAGE_BYTES;
        const int e0 = kc * KC;
        const int row = tid >> 1, q = tid & 1;
        const uint32_t off = (uint32_t)(row * ROWSTRIDE + q * 16);
        const size_t gs = (size_t)row * EE + e0 + q * 8;
        cp16ca(base + OFF_AHI + off, gAhi + gs);  // A: shared with co-resident CTA -> L1
        cp16ca(base + OFF_ALO + off, gAlo + gs);
        cp16cg(base + OFF_BHI + off, gBhi + gs);
        cp16cg(base + OFF_BLO + off, gBlo + gs);
    };

    float acc[4][4][4];
#pragma unroll
    for (int mi = 0; mi < 4; mi++)
#pragma unroll
        for (int ni = 0; ni < 4; ni++)
#pragma unroll
            for (int q = 0; q < 4; q++) acc[mi][ni][q] = 0.0f;

    load_stage(0, 0); asm volatile("cp.async.commit_group;" ::: "memory");
    load_stage(1, 1); asm volatile("cp.async.commit_group;" ::: "memory");
    load_stage(2, 2); asm volatile("cp.async.commit_group;" ::: "memory");

    const int xrow = (lane & 7) + ((lane >> 3) & 1) * 8;  // 0..15
    const uint32_t kb = ((lane >> 4) & 1) * 16;           // byte offset for k8..15

    const uint32_t aRowOff = (uint32_t)((wm * 64 + xrow) * ROWSTRIDE) + kb;
    const uint32_t bRowOff = (uint32_t)((wn * 32 + xrow) * ROWSTRIDE) + kb;

    for (int i = 0; i < NCHUNKS; i++) {
        asm volatile("cp.async.wait_group 2;" ::: "memory");
        __syncthreads();
        if (i + 3 < NCHUNKS) load_stage(i + 3, (i + 3) & 3);
        asm volatile("cp.async.commit_group;" ::: "memory");

        const uint32_t stb = sb + (i & 3) * STAGE_BYTES;
        const uint32_t aR = stb + aRowOff;
        const uint32_t bR = stb + bRowOff;

        uint32_t Ah[4][4], Al[4][4], Bx[2][4];

        // pass 1: hi * hi
#pragma unroll
        for (int mi = 0; mi < 4; mi++)
            ldm_x4(Ah[mi], OFF_AHI + aR + (uint32_t)(mi * 16 * ROWSTRIDE));
#pragma unroll
        for (int nj = 0; nj < 2; nj++)
            ldm_x4(Bx[nj], OFF_BHI + bR + (uint32_t)(nj * 16 * ROWSTRIDE));
#pragma unroll
        for (int mi = 0; mi < 4; mi++)
#pragma unroll
            for (int ni = 0; ni < 4; ni++) {
                int nj = ni >> 1, w = ni & 1;
                mma16816(acc[mi][ni], Ah[mi], Bx[nj][w], Bx[nj][w + 2]);
            }

        // pass 2: lo * hi  (Bx still holds Bhi)
#pragma unroll
        for (int mi = 0; mi < 4; mi++)
            ldm_x4(Al[mi], OFF_ALO + aR + (uint32_t)(mi * 16 * ROWSTRIDE));
#pragma unroll
        for (int mi = 0; mi < 4; mi++)
#pragma unroll
            for (int ni = 0; ni < 4; ni++) {
                int nj = ni >> 1, w = ni & 1;
                mma16816(acc[mi][ni], Al[mi], Bx[nj][w], Bx[nj][w + 2]);
            }

        // pass 3: hi * lo  (reload Bx with Blo; Ah still live)
#pragma unroll
        for (int nj = 0; nj < 2; nj++)
            ldm_x4(Bx[nj], OFF_BLO + bR + (uint32_t)(nj * 16 * ROWSTRIDE));
#pragma unroll
        for (int mi = 0; mi < 4; mi++)
#pragma unroll
            for (int ni = 0; ni < 4; ni++) {
                int nj = ni >> 1, w = ni & 1;
                mma16816(acc[mi][ni], Ah[mi], Bx[nj][w], Bx[nj][w + 2]);
            }

        __syncthreads();
    }

    float* Cb = C + ((size_t)bz * NN + n0 + wm * 64) * MM + m0 + wn * 32;
    const int r = lane >> 2, cc = (lane & 3) * 2;
#pragma unroll
    for (int mi = 0; mi < 4; mi++)
#pragma unroll
        for (int ni = 0; ni < 4; ni++) {
            float* p0 = Cb + (size_t)(mi * 16 + r) * MM + ni * 8 + cc;
            float* p1 = p0 + 8 * MM;
            *(float2*)p0 = make_float2(acc[mi][ni][0], acc[mi][ni][1]);
            *(float2*)p1 = make_float2(acc[mi][ni][2], acc[mi][ni][3]);
        }
}

extern "C" void kernel_launch(void* const* d_in, const int* in_sizes, int n_in,
                              void* d_out, int out_size) {
    const float* A = (const float*)d_in[0];
    const float* B = (const float*)d_in[1];
    float* C = (float*)d_out;

    __nv_bfloat16 *ahi, *alo, *bhi, *blo;
    cudaGetSymbolAddress((void**)&ahi, g_Ahi);
    cudaGetSymbolAddress((void**)&alo, g_Alo);
    cudaGetSymbolAddress((void**)&bhi, g_Bhi);
    cudaGetSymbolAddress((void**)&blo, g_Blo);

    const int cvt_blocks = (2 * (ELEMS / 4) + 255) / 256;
    convert_fused_kernel<<<cvt_blocks, 256>>>(A, B, ahi, alo, bhi, blo);

    cudaFuncSetAttribute(bgemm_mma_kernel, cudaFuncAttributeMaxDynamicSharedMemorySize, SMEM_TOTAL);
    dim3 grid(MM / TILE, NN / TILE, NB);
    bgemm_mma_kernel<<<grid, 256, SMEM_TOTAL>>>(C);
}